// round 6
// baseline (speedup 1.0000x reference)
#include <cuda_runtime.h>
#include <math.h>

#define NN 50000
#define EE 800000
#define DD 64
#define KK 3
#define NKMAX (NN * KK)
#define AGG_EPS 1e-6f
#define BN_EPS  1e-5f
#define XPAD 72
#define SORT_BLOCKS 148

// Scratch (device globals — no allocation allowed)
__device__ float g_Dx[NN * DD];
__device__ float g_Bx[KK * NN * DD];
__device__ float g_xnew[NN * DD];
__device__ float g_fsum[DD];
__device__ float g_fsq[DD];

__device__ int g_count[NKMAX];
__device__ int g_partial[NKMAX];
__device__ int g_blocksum[SORT_BLOCKS];
__device__ int g_segstart[NKMAX + 1];
__device__ int g_cursor[NKMAX];
__device__ int g_sorted[EE];

// grid barrier state (monotonic generation; cnt always returns to 0)
__device__ volatile unsigned g_gen;
__device__ unsigned g_cnt;

__device__ __forceinline__ void grid_barrier(int nb) {
    __syncthreads();
    if (threadIdx.x == 0) {
        __threadfence();
        unsigned gen = g_gen;
        unsigned a = atomicAdd(&g_cnt, 1u);
        if (a == (unsigned)nb - 1u) {
            g_cnt = 0u;
            __threadfence();
            g_gen = gen + 1u;
        } else {
            while (g_gen == gen) { }
        }
    }
    __syncthreads();
}

__device__ __forceinline__ float tanh_fast(float x) {
    float y;
    asm("tanh.approx.f32 %0, %1;" : "=f"(y) : "f"(x));
    return y;
}
__device__ __forceinline__ float sigmoid_fast(float x) {
    return fmaf(tanh_fast(0.5f * x), 0.5f, 0.5f);
}

// ---------------------------------------------------------------------------
// K1 (side stream): fused sort pipeline — zero, hist, scan, scatter.
// grid = 148 blocks x 1024 threads (co-resident; hand-rolled grid barrier).
// ---------------------------------------------------------------------------
__global__ __launch_bounds__(1024) void sort_fused_kernel(
        const int* __restrict__ ei, const int* __restrict__ ea, int N, int E) {
    const int NK = N * KK;
    const int nb = gridDim.x;
    const int b = blockIdx.x;
    const int t = threadIdx.x;
    const int gsz = nb * blockDim.x;
    const int gid = b * blockDim.x + t;

    // Phase 0: zero counts
    for (int i = gid; i < NK; i += gsz) g_count[i] = 0;
    grid_barrier(nb);

    // Phase 1: histogram
    for (int e = gid; e < E; e += gsz) {
        int i  = __ldg(&ei[E + e]);
        int ke = __ldg(&ea[e]) - 1;
        atomicAdd(&g_count[i * KK + ke], 1);
    }
    grid_barrier(nb);

    // Phase 2a: per-block chunk scan
    __shared__ int warpsum[32];
    __shared__ int boff[SORT_BLOCKS];
    const int cb = (NK + nb - 1) / nb;                    // chunk per block
    const int start = b * cb;
    const int idx = start + t;
    int v = (t < cb && idx < NK) ? __ldcg(&g_count[idx]) : 0;

    int lane = t & 31, w = t >> 5;
    int x = v;
    #pragma unroll
    for (int off = 1; off < 32; off <<= 1) {
        int y = __shfl_up_sync(0xffffffff, x, off);
        if (lane >= off) x += y;
    }
    if (lane == 31) warpsum[w] = x;
    __syncthreads();
    if (w == 0) {
        int s = warpsum[lane];
        #pragma unroll
        for (int off = 1; off < 32; off <<= 1) {
            int y = __shfl_up_sync(0xffffffff, s, off);
            if (lane >= off) s += y;
        }
        warpsum[lane] = s;
    }
    __syncthreads();
    int wpre = (w > 0) ? warpsum[w - 1] : 0;
    int incl = x + wpre;
    if (t < cb && idx < NK) g_partial[idx] = incl - v;    // exclusive within chunk
    if (t == blockDim.x - 1) g_blocksum[b] = incl;        // chunk total
    grid_barrier(nb);

    // Phase 2b: every block scans all chunk totals locally, applies offset
    if (t < 32) {
        int acc = 0;
        for (int base = 0; base < nb; base += 32) {
            int i2 = base + t;
            int vv = (i2 < nb) ? __ldcg(&g_blocksum[i2]) : 0;
            int xx = vv;
            #pragma unroll
            for (int off = 1; off < 32; off <<= 1) {
                int y = __shfl_up_sync(0xffffffff, xx, off);
                if (t >= off) xx += y;
            }
            if (i2 < nb) boff[i2] = acc + xx - vv;
            acc += __shfl_sync(0xffffffff, xx, 31);
        }
    }
    __syncthreads();
    if (t < cb && idx < NK) {
        int sv = __ldcg(&g_partial[idx]) + boff[b];
        g_segstart[idx] = sv;
        g_cursor[idx] = sv;
    }
    if (b == 0 && t == 0) g_segstart[NK] = E;
    grid_barrier(nb);

    // Phase 3: scatter
    for (int e = gid; e < E; e += gsz) {
        int j  = __ldg(&ei[e]);
        int i  = __ldg(&ei[E + e]);
        int ke = __ldg(&ea[e]) - 1;
        int pos = atomicAdd(&g_cursor[i * KK + ke], 1);
        g_sorted[pos] = j;
    }
}

// ---------------------------------------------------------------------------
// K2 (main stream): five GEMMs, register-tiled. m=0 (Ax) -> g_xnew.
// ---------------------------------------------------------------------------
__global__ void gemm_kernel(const float* __restrict__ xs,
                            const float* __restrict__ Wa, const float* __restrict__ ba,
                            const float* __restrict__ Wd, const float* __restrict__ bd,
                            const float* __restrict__ Wb, const float* __restrict__ bb,
                            int N) {
    __shared__ float Ws[DD * DD];
    __shared__ float XsT[DD * XPAD];

    int m = blockIdx.y;
    const float* X; const float* W; const float* b; float* dst;
    if (m == 0)      { X = xs + 2 * (size_t)N * DD; W = Wa; b = ba; dst = g_xnew; }
    else if (m == 1) { X = xs + 2 * (size_t)N * DD; W = Wd; b = bd; dst = g_Dx; }
    else {
        int k = m - 2;
        X = xs + (size_t)(2 - k) * N * DD;
        W = Wb + (size_t)k * DD * DD;
        b = bb + k * DD;
        dst = g_Bx + (size_t)k * N * DD;
    }

    int t = threadIdx.x;
    int row0 = blockIdx.x * 64;

    for (int i = t; i < DD * DD; i += 256) Ws[i] = W[i];
    for (int i = t; i < 64 * DD; i += 256) {
        int r  = i >> 6;
        int kk = i & 63;
        int gr = row0 + r;
        XsT[kk * XPAD + r] = (gr < N) ? X[(size_t)gr * DD + kk] : 0.f;
    }
    __syncthreads();

    int tx = t & 15;
    int ty = t >> 4;
    int c0 = tx * 4;
    int r0 = ty * 4;

    float acc[4][4];
    #pragma unroll
    for (int i = 0; i < 4; i++)
        #pragma unroll
        for (int jj = 0; jj < 4; jj++) acc[i][jj] = 0.f;

    #pragma unroll 4
    for (int kk = 0; kk < DD; kk++) {
        float4 av = *(const float4*)&XsT[kk * XPAD + r0];
        float4 bv = *(const float4*)&Ws[kk * DD + c0];
        acc[0][0] += av.x * bv.x; acc[0][1] += av.x * bv.y; acc[0][2] += av.x * bv.z; acc[0][3] += av.x * bv.w;
        acc[1][0] += av.y * bv.x; acc[1][1] += av.y * bv.y; acc[1][2] += av.y * bv.z; acc[1][3] += av.y * bv.w;
        acc[2][0] += av.z * bv.x; acc[2][1] += av.z * bv.y; acc[2][2] += av.z * bv.z; acc[2][3] += av.z * bv.w;
        acc[3][0] += av.w * bv.x; acc[3][1] += av.w * bv.y; acc[3][2] += av.w * bv.z; acc[3][3] += av.w * bv.w;
    }

    float4 bias = *(const float4*)&b[c0];
    #pragma unroll
    for (int i = 0; i < 4; i++) {
        int gr = row0 + r0 + i;
        if (gr < N) {
            float4 o;
            o.x = acc[i][0] + bias.x;
            o.y = acc[i][1] + bias.y;
            o.z = acc[i][2] + bias.z;
            o.w = acc[i][3] + bias.w;
            *(float4*)&dst[(size_t)gr * DD + c0] = o;
        }
    }
}

// ---------------------------------------------------------------------------
// K3: zero BN accumulators (tiny)
// ---------------------------------------------------------------------------
__global__ void bnzero_kernel() {
    int t = threadIdx.x;
    if (t < DD) { g_fsum[t] = 0.f; g_fsq[t] = 0.f; }
}

// ---------------------------------------------------------------------------
// K4: fused aggregation + combine + BN stats.
// One warp per node. Flat edge stream over all 3 k-segments.
// 4 edges per iteration: g = lane>>3 (edge slot), sub = lane&7 (8 dims).
// Software-pipelined gathers (prefetch next quad).
// ---------------------------------------------------------------------------
__global__ void agg_kernel(int N) {
    __shared__ float ssum[DD];
    __shared__ float ssq[DD];
    int t = threadIdx.x;
    if (t < DD) { ssum[t] = 0.f; ssq[t] = 0.f; }
    __syncthreads();

    int warp = (blockIdx.x * blockDim.x + t) >> 5;
    int lane = t & 31;
    int g    = lane >> 3;      // edge slot within quad
    int sub  = lane & 7;       // dim group: dims sub*8 .. sub*8+7

    if (warp < N) {
        int n = warp;
        // segment boundaries [s0, b1, b2, s3]
        int sv = 0;
        if (lane < 4) sv = g_segstart[3 * n + lane];
        int s0 = __shfl_sync(0xffffffff, sv, 0);
        int b1 = __shfl_sync(0xffffffff, sv, 1);
        int b2 = __shfl_sync(0xffffffff, sv, 2);
        int s3 = __shfl_sync(0xffffffff, sv, 3);

        size_t dbase = (size_t)n * DD + sub * 8;
        float4 da = *(const float4*)&g_Dx[dbase];
        float4 db = *(const float4*)&g_Dx[dbase + 4];

        // accumulators: per k, num/den for 8 dims
        float4 n0a = {0,0,0,0}, n0b = {0,0,0,0}, d0a = {0,0,0,0}, d0b = {0,0,0,0};
        float4 n1a = {0,0,0,0}, n1b = {0,0,0,0}, d1a = {0,0,0,0}, d1b = {0,0,0,0};
        float4 n2a = {0,0,0,0}, n2b = {0,0,0,0}, d2a = {0,0,0,0}, d2b = {0,0,0,0};

        const size_t ND = (size_t)N * DD;

        for (int base = s0; base < s3; base += 32) {
            int li = base + lane;
            int jv = (li < s3) ? __ldg(&g_sorted[li]) : 0;
            int cnt = min(32, s3 - base);

            // pipeline: current quad (c), prefetch next (p)
            int q = 0;
            int eidx = base + q + g;
            bool cv = (q + g) < cnt;
            int cj = __shfl_sync(0xffffffff, jv, (q + g) & 31);
            int ck = 0;
            float4 c0 = {0,0,0,0}, c1 = {0,0,0,0};
            if (cv) {
                ck = (eidx >= b2) ? 2 : ((eidx >= b1) ? 1 : 0);
                const float* B = g_Bx + (size_t)ck * ND + (size_t)cj * DD + sub * 8;
                c0 = *(const float4*)B;
                c1 = *(const float4*)(B + 4);
            }

            for (; q < cnt; ) {
                int qn = q + 4;
                // prefetch next quad
                bool pv = false; int pk = 0;
                float4 p0 = {0,0,0,0}, p1 = {0,0,0,0};
                if (qn < cnt) {
                    int eidxn = base + qn + g;
                    pv = (qn + g) < cnt;
                    int pj = __shfl_sync(0xffffffff, jv, (qn + g) & 31);
                    if (pv) {
                        pk = (eidxn >= b2) ? 2 : ((eidxn >= b1) ? 1 : 0);
                        const float* B = g_Bx + (size_t)pk * ND + (size_t)pj * DD + sub * 8;
                        p0 = *(const float4*)B;
                        p1 = *(const float4*)(B + 4);
                    }
                }
                // consume current
                if (cv) {
                    float s0f = sigmoid_fast(da.x + c0.x);
                    float s1f = sigmoid_fast(da.y + c0.y);
                    float s2f = sigmoid_fast(da.z + c0.z);
                    float s3f = sigmoid_fast(da.w + c0.w);
                    float s4f = sigmoid_fast(db.x + c1.x);
                    float s5f = sigmoid_fast(db.y + c1.y);
                    float s6f = sigmoid_fast(db.z + c1.z);
                    float s7f = sigmoid_fast(db.w + c1.w);
                    float4 pa, pb, sa, sb;
                    pa.x = s0f * c0.x; pa.y = s1f * c0.y; pa.z = s2f * c0.z; pa.w = s3f * c0.w;
                    pb.x = s4f * c1.x; pb.y = s5f * c1.y; pb.z = s6f * c1.z; pb.w = s7f * c1.w;
                    sa.x = s0f; sa.y = s1f; sa.z = s2f; sa.w = s3f;
                    sb.x = s4f; sb.y = s5f; sb.z = s6f; sb.w = s7f;
                    if (ck == 0) {
                        n0a.x += pa.x; n0a.y += pa.y; n0a.z += pa.z; n0a.w += pa.w;
                        n0b.x += pb.x; n0b.y += pb.y; n0b.z += pb.z; n0b.w += pb.w;
                        d0a.x += sa.x; d0a.y += sa.y; d0a.z += sa.z; d0a.w += sa.w;
                        d0b.x += sb.x; d0b.y += sb.y; d0b.z += sb.z; d0b.w += sb.w;
                    } else if (ck == 1) {
                        n1a.x += pa.x; n1a.y += pa.y; n1a.z += pa.z; n1a.w += pa.w;
                        n1b.x += pb.x; n1b.y += pb.y; n1b.z += pb.z; n1b.w += pb.w;
                        d1a.x += sa.x; d1a.y += sa.y; d1a.z += sa.z; d1a.w += sa.w;
                        d1b.x += sb.x; d1b.y += sb.y; d1b.z += sb.z; d1b.w += sb.w;
                    } else {
                        n2a.x += pa.x; n2a.y += pa.y; n2a.z += pa.z; n2a.w += pa.w;
                        n2b.x += pb.x; n2b.y += pb.y; n2b.z += pb.z; n2b.w += pb.w;
                        d2a.x += sa.x; d2a.y += sa.y; d2a.z += sa.z; d2a.w += sa.w;
                        d2b.x += sb.x; d2b.y += sb.y; d2b.z += sb.z; d2b.w += sb.w;
                    }
                }
                c0 = p0; c1 = p1; ck = pk; cv = pv;
                q = qn;
            }
        }

        // reduce over the 4 edge slots (lane bits 3,4)
        #define XRED(v) \
            v.x += __shfl_xor_sync(0xffffffff, v.x, 8);  v.y += __shfl_xor_sync(0xffffffff, v.y, 8); \
            v.z += __shfl_xor_sync(0xffffffff, v.z, 8);  v.w += __shfl_xor_sync(0xffffffff, v.w, 8); \
            v.x += __shfl_xor_sync(0xffffffff, v.x, 16); v.y += __shfl_xor_sync(0xffffffff, v.y, 16); \
            v.z += __shfl_xor_sync(0xffffffff, v.z, 16); v.w += __shfl_xor_sync(0xffffffff, v.w, 16);
        XRED(n0a) XRED(n0b) XRED(d0a) XRED(d0b)
        XRED(n1a) XRED(n1b) XRED(d1a) XRED(d1b)
        XRED(n2a) XRED(n2b) XRED(d2a) XRED(d2b)
        #undef XRED

        float4 ea, eb;
        ea.x = __fdividef(n0a.x, d0a.x + AGG_EPS) + __fdividef(n1a.x, d1a.x + AGG_EPS) + __fdividef(n2a.x, d2a.x + AGG_EPS);
        ea.y = __fdividef(n0a.y, d0a.y + AGG_EPS) + __fdividef(n1a.y, d1a.y + AGG_EPS) + __fdividef(n2a.y, d2a.y + AGG_EPS);
        ea.z = __fdividef(n0a.z, d0a.z + AGG_EPS) + __fdividef(n1a.z, d1a.z + AGG_EPS) + __fdividef(n2a.z, d2a.z + AGG_EPS);
        ea.w = __fdividef(n0a.w, d0a.w + AGG_EPS) + __fdividef(n1a.w, d1a.w + AGG_EPS) + __fdividef(n2a.w, d2a.w + AGG_EPS);
        eb.x = __fdividef(n0b.x, d0b.x + AGG_EPS) + __fdividef(n1b.x, d1b.x + AGG_EPS) + __fdividef(n2b.x, d2b.x + AGG_EPS);
        eb.y = __fdividef(n0b.y, d0b.y + AGG_EPS) + __fdividef(n1b.y, d1b.y + AGG_EPS) + __fdividef(n2b.y, d2b.y + AGG_EPS);
        eb.z = __fdividef(n0b.z, d0b.z + AGG_EPS) + __fdividef(n1b.z, d1b.z + AGG_EPS) + __fdividef(n2b.z, d2b.z + AGG_EPS);
        eb.w = __fdividef(n0b.w, d0b.w + AGG_EPS) + __fdividef(n1b.w, d1b.w + AGG_EPS) + __fdividef(n2b.w, d2b.w + AGG_EPS);

        float4 aa = *(const float4*)&g_xnew[dbase];
        float4 ab = *(const float4*)&g_xnew[dbase + 4];
        float4 va, vb;
        va.x = aa.x + ea.x * (1.f / KK);
        va.y = aa.y + ea.y * (1.f / KK);
        va.z = aa.z + ea.z * (1.f / KK);
        va.w = aa.w + ea.w * (1.f / KK);
        vb.x = ab.x + eb.x * (1.f / KK);
        vb.y = ab.y + eb.y * (1.f / KK);
        vb.z = ab.z + eb.z * (1.f / KK);
        vb.w = ab.w + eb.w * (1.f / KK);

        if (g == 0) {
            *(float4*)&g_xnew[dbase]     = va;
            *(float4*)&g_xnew[dbase + 4] = vb;
        } else if (g == 1) {
            atomicAdd(&ssum[sub * 8 + 0], va.x);
            atomicAdd(&ssum[sub * 8 + 1], va.y);
            atomicAdd(&ssum[sub * 8 + 2], va.z);
            atomicAdd(&ssum[sub * 8 + 3], va.w);
            atomicAdd(&ssum[sub * 8 + 4], vb.x);
            atomicAdd(&ssum[sub * 8 + 5], vb.y);
            atomicAdd(&ssum[sub * 8 + 6], vb.z);
            atomicAdd(&ssum[sub * 8 + 7], vb.w);
        } else if (g == 2) {
            atomicAdd(&ssq[sub * 8 + 0], va.x * va.x);
            atomicAdd(&ssq[sub * 8 + 1], va.y * va.y);
            atomicAdd(&ssq[sub * 8 + 2], va.z * va.z);
            atomicAdd(&ssq[sub * 8 + 3], va.w * va.w);
            atomicAdd(&ssq[sub * 8 + 4], vb.x * vb.x);
            atomicAdd(&ssq[sub * 8 + 5], vb.y * vb.y);
            atomicAdd(&ssq[sub * 8 + 6], vb.z * vb.z);
            atomicAdd(&ssq[sub * 8 + 7], vb.w * vb.w);
        }
    }
    __syncthreads();
    if (t < DD) {
        atomicAdd(&g_fsum[t], ssum[t]);
        atomicAdd(&g_fsq[t],  ssq[t]);
    }
}

// ---------------------------------------------------------------------------
// K5: BatchNorm + ReLU (vectorized)
// ---------------------------------------------------------------------------
__global__ void bn_kernel(const float* __restrict__ gamma,
                          const float* __restrict__ beta,
                          float* __restrict__ out, int N) {
    int idx = blockIdx.x * blockDim.x + threadIdx.x;   // float4 index
    if (idx >= N * (DD / 4)) return;
    int d4 = (idx & 15) * 4;
    float invN = 1.f / (float)N;
    float4 x = *(const float4*)&g_xnew[(size_t)idx * 4];
    float4 o;
    #pragma unroll
    for (int i = 0; i < 4; i++) {
        int d = d4 + i;
        float mean = g_fsum[d] * invN;
        float var  = g_fsq[d] * invN - mean * mean;
        float xi = (i == 0) ? x.x : (i == 1) ? x.y : (i == 2) ? x.z : x.w;
        float y = gamma[d] * (xi - mean) * rsqrtf(var + BN_EPS) + beta[d];
        y = fmaxf(y, 0.f);
        if (i == 0) o.x = y; else if (i == 1) o.y = y; else if (i == 2) o.z = y; else o.w = y;
    }
    *(float4*)&out[(size_t)idx * 4] = o;
}

// ---------------------------------------------------------------------------
extern "C" void kernel_launch(void* const* d_in, const int* in_sizes, int n_in,
                              void* d_out, int out_size) {
    const float* xs    = (const float*)d_in[0];
    const int*   ei    = (const int*)d_in[1];
    const int*   ea    = (const int*)d_in[2];
    const float* Wa    = (const float*)d_in[3];
    const float* ba    = (const float*)d_in[4];
    const float* Wd    = (const float*)d_in[5];
    const float* bd    = (const float*)d_in[6];
    const float* Wb    = (const float*)d_in[7];
    const float* bb    = (const float*)d_in[8];
    const float* gamma = (const float*)d_in[9];
    const float* beta  = (const float*)d_in[10];
    float* out = (float*)d_out;

    int N = in_sizes[0] / (3 * DD);
    int E = in_sizes[2];

    static cudaStream_t side = nullptr;
    static cudaEvent_t evFork = nullptr, evJoin = nullptr;
    if (!side) {
        cudaStreamCreateWithFlags(&side, cudaStreamNonBlocking);
        cudaEventCreateWithFlags(&evFork, cudaEventDisableTiming);
        cudaEventCreateWithFlags(&evJoin, cudaEventDisableTiming);
    }

    cudaEventRecord(evFork, 0);
    cudaStreamWaitEvent(side, evFork, 0);

    // launch #1 (side): fused sort
    sort_fused_kernel<<<SORT_BLOCKS, 1024, 0, side>>>(ei, ea, N, E);

    // launch #2 (main): GEMMs (overlapped with sort)
    dim3 gGemm((N + 63) / 64, 5);
    gemm_kernel<<<gGemm, 256>>>(xs, Wa, ba, Wd, bd, Wb, bb, N);

    // launch #3 (main): BN accumulator zero
    bnzero_kernel<<<1, 128>>>();

    cudaEventRecord(evJoin, side);
    cudaStreamWaitEvent(0, evJoin, 0);

    // launch #4 (main): aggregation (profiled by ncu)
    agg_kernel<<<(N * 32 + 255) / 256, 256>>>(N);

    // launch #5 (main): BN + ReLU
    bn_kernel<<<(N * (DD / 4) + 255) / 256, 256>>>(gamma, beta, out, N);
}

// round 7
// speedup vs baseline: 1.4967x; 1.4967x over previous
#include <cuda_runtime.h>
#include <math.h>

#define NN 50000
#define EE 800000
#define DD 64
#define KK 3
#define NKMAX (NN * KK)
#define AGG_EPS 1e-6f
#define BN_EPS  1e-5f
#define SCAN_BLK 1024
#define MAXBLKS 256
#define XPAD 72

// Scratch (device globals — no allocation allowed)
__device__ float g_Dx[NN * DD];
__device__ float g_Bx[KK * NN * DD];
__device__ float g_xnew[NN * DD];     // gemm writes Ax; agg overwrites with x_new
__device__ float g_fsum[DD];
__device__ float g_fsq[DD];

__device__ int g_count[NKMAX];
__device__ int g_partial[NKMAX];
__device__ int g_blocksum[MAXBLKS];
__device__ int g_segstart[NKMAX + 1];
__device__ int g_cursor[NKMAX];
__device__ int g_sorted[EE];

__device__ __forceinline__ float tanh_fast(float x) {
    float y;
    asm("tanh.approx.f32 %0, %1;" : "=f"(y) : "f"(x));
    return y;
}
__device__ __forceinline__ float sigmoid_fast(float x) {
    return fmaf(tanh_fast(0.5f * x), 0.5f, 0.5f);
}

// ---------------------------------------------------------------------------
// K0: zero histogram + BN accumulators
// ---------------------------------------------------------------------------
__global__ void zero_kernel(int NK) {
    int idx = blockIdx.x * blockDim.x + threadIdx.x;
    int stride = gridDim.x * blockDim.x;
    for (int i = idx; i < NK; i += stride) g_count[i] = 0;
    if (idx < DD) { g_fsum[idx] = 0.f; g_fsq[idx] = 0.f; }
}

// ---------------------------------------------------------------------------
// K1: histogram of edges per segment (seg = i*K + ke)
// ---------------------------------------------------------------------------
__global__ void hist_kernel(const int* __restrict__ ei, const int* __restrict__ ea, int E) {
    int e = blockIdx.x * blockDim.x + threadIdx.x;
    if (e >= E) return;
    int i  = ei[E + e];
    int ke = ea[e] - 1;
    atomicAdd(&g_count[i * KK + ke], 1);
}

// ---------------------------------------------------------------------------
// K2a: per-block exclusive scan (shfl-based)
// ---------------------------------------------------------------------------
__global__ void scan1_kernel(int NK) {
    __shared__ int warpsum[32];
    int t = threadIdx.x;
    int lane = t & 31;
    int w = t >> 5;
    int idx = blockIdx.x * SCAN_BLK + t;
    int v = (idx < NK) ? g_count[idx] : 0;

    int x = v;
    #pragma unroll
    for (int off = 1; off < 32; off <<= 1) {
        int y = __shfl_up_sync(0xffffffff, x, off);
        if (lane >= off) x += y;
    }
    if (lane == 31) warpsum[w] = x;
    __syncthreads();
    if (w == 0) {
        int s = (lane < SCAN_BLK / 32) ? warpsum[lane] : 0;
        #pragma unroll
        for (int off = 1; off < 32; off <<= 1) {
            int y = __shfl_up_sync(0xffffffff, s, off);
            if (lane >= off) s += y;
        }
        if (lane < SCAN_BLK / 32) warpsum[lane] = s;
    }
    __syncthreads();
    int wpre = (w > 0) ? warpsum[w - 1] : 0;
    int incl = x + wpre;
    if (idx < NK) g_partial[idx] = incl - v;
    if (t == SCAN_BLK - 1) g_blocksum[blockIdx.x] = incl;
}

// K2b: fused block-offset scan + apply
__global__ void scan23_kernel(int NK, int E, int nblocks) {
    __shared__ int boff[MAXBLKS];
    int t = threadIdx.x;
    if (t < 32) {
        int acc = 0;
        for (int base = 0; base < nblocks; base += 32) {
            int idx = base + t;
            int v = (idx < nblocks) ? g_blocksum[idx] : 0;
            int x = v;
            #pragma unroll
            for (int off = 1; off < 32; off <<= 1) {
                int y = __shfl_up_sync(0xffffffff, x, off);
                if (t >= off) x += y;
            }
            if (idx < nblocks) boff[idx] = acc + x - v;
            acc += __shfl_sync(0xffffffff, x, 31);
        }
    }
    __syncthreads();
    int idx = blockIdx.x * blockDim.x + t;
    if (idx < NK) {
        int v = g_partial[idx] + boff[idx >> 10];
        g_segstart[idx] = v;
        g_cursor[idx] = v;
    }
    if (idx == 0) g_segstart[NK] = E;
}

// ---------------------------------------------------------------------------
// K3: scatter source node ids into sorted order
// ---------------------------------------------------------------------------
__global__ void scatter_kernel(const int* __restrict__ ei, const int* __restrict__ ea, int E) {
    int e = blockIdx.x * blockDim.x + threadIdx.x;
    if (e >= E) return;
    int j  = ei[e];
    int i  = ei[E + e];
    int ke = ea[e] - 1;
    int pos = atomicAdd(&g_cursor[i * KK + ke], 1);
    g_sorted[pos] = j;
}

// ---------------------------------------------------------------------------
// K4: five GEMMs, register-tiled 64x64 per 256-thread block, 4x4 per thread.
// m=0 (Ax) writes into g_xnew.
// ---------------------------------------------------------------------------
__global__ void gemm_kernel(const float* __restrict__ xs,
                            const float* __restrict__ Wa, const float* __restrict__ ba,
                            const float* __restrict__ Wd, const float* __restrict__ bd,
                            const float* __restrict__ Wb, const float* __restrict__ bb,
                            int N) {
    __shared__ float Ws[DD * DD];
    __shared__ float XsT[DD * XPAD];

    int m = blockIdx.y;
    const float* X; const float* W; const float* b; float* dst;
    if (m == 0)      { X = xs + 2 * (size_t)N * DD; W = Wa; b = ba; dst = g_xnew; }
    else if (m == 1) { X = xs + 2 * (size_t)N * DD; W = Wd; b = bd; dst = g_Dx; }
    else {
        int k = m - 2;
        X = xs + (size_t)(2 - k) * N * DD;
        W = Wb + (size_t)k * DD * DD;
        b = bb + k * DD;
        dst = g_Bx + (size_t)k * N * DD;
    }

    int t = threadIdx.x;
    int row0 = blockIdx.x * 64;

    for (int i = t; i < DD * DD; i += 256) Ws[i] = W[i];
    for (int i = t; i < 64 * DD; i += 256) {
        int r  = i >> 6;
        int kk = i & 63;
        int gr = row0 + r;
        XsT[kk * XPAD + r] = (gr < N) ? X[(size_t)gr * DD + kk] : 0.f;
    }
    __syncthreads();

    int tx = t & 15;
    int ty = t >> 4;
    int c0 = tx * 4;
    int r0 = ty * 4;

    float acc[4][4];
    #pragma unroll
    for (int i = 0; i < 4; i++)
        #pragma unroll
        for (int jj = 0; jj < 4; jj++) acc[i][jj] = 0.f;

    #pragma unroll 4
    for (int kk = 0; kk < DD; kk++) {
        float4 av = *(const float4*)&XsT[kk * XPAD + r0];
        float4 bv = *(const float4*)&Ws[kk * DD + c0];
        acc[0][0] += av.x * bv.x; acc[0][1] += av.x * bv.y; acc[0][2] += av.x * bv.z; acc[0][3] += av.x * bv.w;
        acc[1][0] += av.y * bv.x; acc[1][1] += av.y * bv.y; acc[1][2] += av.y * bv.z; acc[1][3] += av.y * bv.w;
        acc[2][0] += av.z * bv.x; acc[2][1] += av.z * bv.y; acc[2][2] += av.z * bv.z; acc[2][3] += av.z * bv.w;
        acc[3][0] += av.w * bv.x; acc[3][1] += av.w * bv.y; acc[3][2] += av.w * bv.z; acc[3][3] += av.w * bv.w;
    }

    float4 bias = *(const float4*)&b[c0];
    #pragma unroll
    for (int i = 0; i < 4; i++) {
        int gr = row0 + r0 + i;
        if (gr < N) {
            float4 o;
            o.x = acc[i][0] + bias.x;
            o.y = acc[i][1] + bias.y;
            o.z = acc[i][2] + bias.z;
            o.w = acc[i][3] + bias.w;
            *(float4*)&dst[(size_t)gr * DD + c0] = o;
        }
    }
}

// ---------------------------------------------------------------------------
// K5: fused aggregation + combine + BN stats.
// One warp per node; lane owns 2 dims (float2). Per-k segment loop keeps
// live accumulators small (regs ~40 -> high occupancy). Edge chunk manually
// unrolled x4: the 4 gather addresses come from registers (jv), so 4
// independent LDG.64 issue back-to-back => MLP=4 per warp.
// ---------------------------------------------------------------------------
__global__ void agg_kernel(int N) {
    __shared__ float ssum[DD];
    __shared__ float ssq[DD];
    int t = threadIdx.x;
    if (t < DD) { ssum[t] = 0.f; ssq[t] = 0.f; }
    __syncthreads();

    int warp = (blockIdx.x * blockDim.x + t) >> 5;
    int lane = t & 31;

    if (warp < N) {
        int n = warp;
        float2 d = *(const float2*)&g_Dx[(size_t)n * DD + lane * 2];

        int sv = 0;
        if (lane < 4) sv = __ldg(&g_segstart[3 * n + lane]);
        int seg0 = __shfl_sync(0xffffffff, sv, 0);
        int seg1 = __shfl_sync(0xffffffff, sv, 1);
        int seg2 = __shfl_sync(0xffffffff, sv, 2);
        int seg3 = __shfl_sync(0xffffffff, sv, 3);

        float eta0 = 0.f, eta1 = 0.f;

        #pragma unroll
        for (int k = 0; k < KK; k++) {
            int s = (k == 0) ? seg0 : (k == 1) ? seg1 : seg2;
            int e = (k == 0) ? seg1 : (k == 1) ? seg2 : seg3;
            const float* Bk = g_Bx + (size_t)k * N * DD + lane * 2;

            float num0 = 0.f, num1 = 0.f, den0 = 0.f, den1 = 0.f;

            for (int base = s; base < e; base += 32) {
                int li = base + lane;
                int jv = (li < e) ? __ldg(&g_sorted[li]) : 0;
                int cnt = min(32, e - base);
                int m = 0;
                for (; m + 4 <= cnt; m += 4) {
                    int j0 = __shfl_sync(0xffffffff, jv, m);
                    int j1 = __shfl_sync(0xffffffff, jv, m + 1);
                    int j2 = __shfl_sync(0xffffffff, jv, m + 2);
                    int j3 = __shfl_sync(0xffffffff, jv, m + 3);
                    float2 b0 = *(const float2*)(Bk + (size_t)j0 * DD);
                    float2 b1 = *(const float2*)(Bk + (size_t)j1 * DD);
                    float2 b2 = *(const float2*)(Bk + (size_t)j2 * DD);
                    float2 b3 = *(const float2*)(Bk + (size_t)j3 * DD);
                    float sa, sb;
                    sa = sigmoid_fast(d.x + b0.x); sb = sigmoid_fast(d.y + b0.y);
                    num0 += sa * b0.x; den0 += sa; num1 += sb * b0.y; den1 += sb;
                    sa = sigmoid_fast(d.x + b1.x); sb = sigmoid_fast(d.y + b1.y);
                    num0 += sa * b1.x; den0 += sa; num1 += sb * b1.y; den1 += sb;
                    sa = sigmoid_fast(d.x + b2.x); sb = sigmoid_fast(d.y + b2.y);
                    num0 += sa * b2.x; den0 += sa; num1 += sb * b2.y; den1 += sb;
                    sa = sigmoid_fast(d.x + b3.x); sb = sigmoid_fast(d.y + b3.y);
                    num0 += sa * b3.x; den0 += sa; num1 += sb * b3.y; den1 += sb;
                }
                for (; m < cnt; m++) {
                    int j = __shfl_sync(0xffffffff, jv, m);
                    float2 b = *(const float2*)(Bk + (size_t)j * DD);
                    float sa = sigmoid_fast(d.x + b.x);
                    float sb = sigmoid_fast(d.y + b.y);
                    num0 += sa * b.x; den0 += sa;
                    num1 += sb * b.y; den1 += sb;
                }
            }
            eta0 += __fdividef(num0, den0 + AGG_EPS);
            eta1 += __fdividef(num1, den1 + AGG_EPS);
        }

        size_t obase = (size_t)n * DD + lane * 2;
        float2 a = *(const float2*)&g_xnew[obase];   // Ax
        float v0 = a.x + eta0 * (1.f / KK);
        float v1 = a.y + eta1 * (1.f / KK);
        float2 vo; vo.x = v0; vo.y = v1;
        *(float2*)&g_xnew[obase] = vo;

        atomicAdd(&ssum[lane * 2 + 0], v0);
        atomicAdd(&ssum[lane * 2 + 1], v1);
        atomicAdd(&ssq[lane * 2 + 0], v0 * v0);
        atomicAdd(&ssq[lane * 2 + 1], v1 * v1);
    }
    __syncthreads();
    if (t < DD) {
        atomicAdd(&g_fsum[t], ssum[t]);
        atomicAdd(&g_fsq[t],  ssq[t]);
    }
}

// ---------------------------------------------------------------------------
// K6: BatchNorm + ReLU (vectorized)
// ---------------------------------------------------------------------------
__global__ void bn_kernel(const float* __restrict__ gamma,
                          const float* __restrict__ beta,
                          float* __restrict__ out, int N) {
    int idx = blockIdx.x * blockDim.x + threadIdx.x;   // float4 index
    if (idx >= N * (DD / 4)) return;
    int d4 = (idx & 15) * 4;
    float invN = 1.f / (float)N;
    float4 x = *(const float4*)&g_xnew[(size_t)idx * 4];
    float4 o;
    #pragma unroll
    for (int i = 0; i < 4; i++) {
        int d = d4 + i;
        float mean = g_fsum[d] * invN;
        float var  = g_fsq[d] * invN - mean * mean;
        float xi = (i == 0) ? x.x : (i == 1) ? x.y : (i == 2) ? x.z : x.w;
        float y = gamma[d] * (xi - mean) * rsqrtf(var + BN_EPS) + beta[d];
        y = fmaxf(y, 0.f);
        if (i == 0) o.x = y; else if (i == 1) o.y = y; else if (i == 2) o.z = y; else o.w = y;
    }
    *(float4*)&out[(size_t)idx * 4] = o;
}

// ---------------------------------------------------------------------------
extern "C" void kernel_launch(void* const* d_in, const int* in_sizes, int n_in,
                              void* d_out, int out_size) {
    const float* xs    = (const float*)d_in[0];
    const int*   ei    = (const int*)d_in[1];
    const int*   ea    = (const int*)d_in[2];
    const float* Wa    = (const float*)d_in[3];
    const float* ba    = (const float*)d_in[4];
    const float* Wd    = (const float*)d_in[5];
    const float* bd    = (const float*)d_in[6];
    const float* Wb    = (const float*)d_in[7];
    const float* bb    = (const float*)d_in[8];
    const float* gamma = (const float*)d_in[9];
    const float* beta  = (const float*)d_in[10];
    float* out = (float*)d_out;

    int N = in_sizes[0] / (3 * DD);
    int E = in_sizes[2];
    int NK = N * KK;
    int nScanBlks = (NK + SCAN_BLK - 1) / SCAN_BLK;

    static cudaStream_t side = nullptr;
    static cudaEvent_t evFork = nullptr, evJoin = nullptr;
    if (!side) {
        cudaStreamCreateWithFlags(&side, cudaStreamNonBlocking);
        cudaEventCreateWithFlags(&evFork, cudaEventDisableTiming);
        cudaEventCreateWithFlags(&evJoin, cudaEventDisableTiming);
    }

    cudaEventRecord(evFork, 0);
    cudaStreamWaitEvent(side, evFork, 0);

    zero_kernel<<<256, 256, 0, side>>>(NK);
    hist_kernel<<<(E + 255) / 256, 256, 0, side>>>(ei, ea, E);
    scan1_kernel<<<nScanBlks, SCAN_BLK, 0, side>>>(NK);
    scan23_kernel<<<(NK + 255) / 256, 256, 0, side>>>(NK, E, nScanBlks);
    scatter_kernel<<<(E + 255) / 256, 256, 0, side>>>(ei, ea, E);

    dim3 gGemm((N + 63) / 64, 5);
    gemm_kernel<<<gGemm, 256>>>(xs, Wa, ba, Wd, bd, Wb, bb, N);

    cudaEventRecord(evJoin, side);
    cudaStreamWaitEvent(0, evJoin, 0);

    agg_kernel<<<(N * 32 + 255) / 256, 256>>>(N);

    bn_kernel<<<(N * (DD / 4) + 255) / 256, 256>>>(gamma, beta, out, N);
}